// round 1
// baseline (speedup 1.0000x reference)
#include <cuda_runtime.h>
#include <cuda_bf16.h>
#include <math.h>

// Problem constants
#define B_ 4
#define T_ 2048
#define C_ 1024
#define H_ 16
#define D_ 64
#define M_ (B_ * T_)          // 8192 rows
#define QKV_N (3 * C_)        // 3072

// Scratch (static device allocations are allowed; cudaMalloc is not)
__device__ float g_qkv[(size_t)M_ * QKV_N];   // [B*T, 3C], q|k|v interleaved per row
__device__ float g_ctx[(size_t)M_ * C_];      // [B*T, C] attention output

// ---------------------------------------------------------------------------
// NT GEMM: C[m][n] = sum_k A[m][k] * W[n][k] + bias[n]
// A: [M,K] row-major, W: [N,K] row-major (torch Linear weight layout).
// Tiles: BM=64, BN=64, BK=16. 256 threads, 4x4 register micro-tile each.
// ---------------------------------------------------------------------------
__global__ void __launch_bounds__(256) gemm_nt_kernel(
    const float* __restrict__ A, const float* __restrict__ W,
    const float* __restrict__ bias, float* __restrict__ Cmat,
    int M, int N, int K)
{
    const int BM = 64, BN = 64, BK = 16;
    __shared__ __align__(16) float As[BK][BM + 4];  // As[k][m]
    __shared__ __align__(16) float Bs[BK][BN + 4];  // Bs[k][n]

    const int tid = threadIdx.x;
    const int tx = tid & 15;        // n micro index
    const int ty = tid >> 4;        // m micro index
    const int m0 = blockIdx.y * BM;
    const int n0 = blockIdx.x * BN;

    // load mapping: each thread loads one float4 of A and one of W per BK step
    const int lr = tid >> 2;              // 0..63 tile row
    const int lc = (tid & 3) << 2;        // 0,4,8,12 (k offset)
    const float* Aptr = A + (size_t)(m0 + lr) * K + lc;
    const float* Wptr = W + (size_t)(n0 + lr) * K + lc;

    float acc[4][4] = {};

    for (int k0 = 0; k0 < K; k0 += BK) {
        float4 av = *(const float4*)(Aptr + k0);
        float4 wv = *(const float4*)(Wptr + k0);
        As[lc + 0][lr] = av.x; As[lc + 1][lr] = av.y;
        As[lc + 2][lr] = av.z; As[lc + 3][lr] = av.w;
        Bs[lc + 0][lr] = wv.x; Bs[lc + 1][lr] = wv.y;
        Bs[lc + 2][lr] = wv.z; Bs[lc + 3][lr] = wv.w;
        __syncthreads();

        #pragma unroll
        for (int kk = 0; kk < BK; kk++) {
            float4 a4 = *(const float4*)&As[kk][ty * 4];
            float4 b4 = *(const float4*)&Bs[kk][tx * 4];
            float a[4] = {a4.x, a4.y, a4.z, a4.w};
            float b[4] = {b4.x, b4.y, b4.z, b4.w};
            #pragma unroll
            for (int i = 0; i < 4; i++)
                #pragma unroll
                for (int j = 0; j < 4; j++)
                    acc[i][j] = fmaf(a[i], b[j], acc[i][j]);
        }
        __syncthreads();
    }

    float4 bv = *(const float4*)&bias[n0 + tx * 4];
    float bb[4] = {bv.x, bv.y, bv.z, bv.w};
    #pragma unroll
    for (int i = 0; i < 4; i++) {
        float4 o;
        o.x = acc[i][0] + bb[0];
        o.y = acc[i][1] + bb[1];
        o.z = acc[i][2] + bb[2];
        o.w = acc[i][3] + bb[3];
        *(float4*)&Cmat[(size_t)(m0 + ty * 4 + i) * N + n0 + tx * 4] = o;
    }
}

// ---------------------------------------------------------------------------
// Flash attention (fp32, causal). One block = one (b, h, 64-row q-tile).
// 256 threads as 16x16; each thread owns a 4x4 S/O micro-tile.
// Q,K stored transposed in smem with a 4-wide XOR swizzle (store conflicts
// drop 8-way -> 2-way; reads stay broadcast / conflict-free).
// ---------------------------------------------------------------------------
#define SMS 68   // smem row stride (floats)

__device__ __forceinline__ int qk_slot(int d, int r) {
    // transposed + swizzled slot for element (d, r)
    int s4 = ((d >> 2) & 15) << 2;
    return d * SMS + (((r & 60) ^ s4) | (r & 3));
}

__global__ void __launch_bounds__(256) attn_kernel(
    const float* __restrict__ qkv, float* __restrict__ ctx)
{
    extern __shared__ __align__(16) float sm[];
    float* Qt = sm;                  // [64][SMS] Qt[d][r] (swizzled)
    float* Kt = sm + 64 * SMS;       // [64][SMS] Kt[d][c] (swizzled)
    float* Vs = sm + 2 * 64 * SMS;   // [64][SMS] Vs[k][d] (natural)
    float* Ps = sm + 3 * 64 * SMS;   // [64][SMS] Ps[row][k]

    const int tid = threadIdx.x;
    const int tx = tid & 15;
    const int ty = tid >> 4;
    const int q0 = blockIdx.x * 64;
    const int h  = blockIdx.y;
    const int b  = blockIdx.z;

    const size_t base = (size_t)b * T_ * QKV_N + (size_t)h * D_;

    // ---- load Q tile (transposed + swizzled) ----
    #pragma unroll
    for (int i = 0; i < 4; i++) {
        int idx = tid + i * 256;            // 0..1023
        int r = idx >> 4;                   // 0..63
        int d4 = (idx & 15) << 2;           // 0..60
        float4 v = *(const float4*)&qkv[base + (size_t)(q0 + r) * QKV_N + d4];
        Qt[qk_slot(d4 + 0, r)] = v.x;
        Qt[qk_slot(d4 + 1, r)] = v.y;
        Qt[qk_slot(d4 + 2, r)] = v.z;
        Qt[qk_slot(d4 + 3, r)] = v.w;
    }

    float o[4][4] = {};
    float mi[4] = {-1e30f, -1e30f, -1e30f, -1e30f};
    float li[4] = {};

    for (int k0 = 0; k0 <= q0; k0 += 64) {
        // ---- load K (transposed+swizzled) and V (natural) tiles ----
        #pragma unroll
        for (int i = 0; i < 4; i++) {
            int idx = tid + i * 256;
            int r = idx >> 4;
            int d4 = (idx & 15) << 2;
            size_t rowoff = base + (size_t)(k0 + r) * QKV_N;
            float4 kv = *(const float4*)&qkv[rowoff + C_ + d4];
            Kt[qk_slot(d4 + 0, r)] = kv.x;
            Kt[qk_slot(d4 + 1, r)] = kv.y;
            Kt[qk_slot(d4 + 2, r)] = kv.z;
            Kt[qk_slot(d4 + 3, r)] = kv.w;
            float4 vv = *(const float4*)&qkv[rowoff + 2 * C_ + d4];
            *(float4*)&Vs[r * SMS + d4] = vv;
        }
        __syncthreads();

        // ---- S = Q K^T (scaled) ----
        float s[4][4] = {};
        #pragma unroll 16
        for (int d = 0; d < 64; d++) {
            int s4 = ((d >> 2) & 15) << 2;
            float4 qa = *(const float4*)&Qt[d * SMS + ((ty * 4) ^ s4)];
            float4 kb = *(const float4*)&Kt[d * SMS + ((tx * 4) ^ s4)];
            float qv[4] = {qa.x, qa.y, qa.z, qa.w};
            float kv[4] = {kb.x, kb.y, kb.z, kb.w};
            #pragma unroll
            for (int i = 0; i < 4; i++)
                #pragma unroll
                for (int j = 0; j < 4; j++)
                    s[i][j] = fmaf(qv[i], kv[j], s[i][j]);
        }

        const bool diag = (k0 == q0);
        #pragma unroll
        for (int i = 0; i < 4; i++) {
            int row = ty * 4 + i;
            #pragma unroll
            for (int j = 0; j < 4; j++) {
                float val = s[i][j] * 0.125f;   // 1/sqrt(64)
                if (diag && (tx * 4 + j > row)) val = -1e30f;
                s[i][j] = val;
            }
        }

        // ---- online softmax (row reductions across the 16 tx lanes) ----
        #pragma unroll
        for (int i = 0; i < 4; i++) {
            float mx = fmaxf(fmaxf(s[i][0], s[i][1]), fmaxf(s[i][2], s[i][3]));
            #pragma unroll
            for (int off = 1; off < 16; off <<= 1)
                mx = fmaxf(mx, __shfl_xor_sync(0xffffffffu, mx, off));
            float mnew = fmaxf(mi[i], mx);
            float alpha = __expf(mi[i] - mnew);
            float p0 = __expf(s[i][0] - mnew);
            float p1 = __expf(s[i][1] - mnew);
            float p2 = __expf(s[i][2] - mnew);
            float p3 = __expf(s[i][3] - mnew);
            float rs = (p0 + p1) + (p2 + p3);
            #pragma unroll
            for (int off = 1; off < 16; off <<= 1)
                rs += __shfl_xor_sync(0xffffffffu, rs, off);
            li[i] = li[i] * alpha + rs;
            mi[i] = mnew;
            o[i][0] *= alpha; o[i][1] *= alpha;
            o[i][2] *= alpha; o[i][3] *= alpha;
            float4 pv4 = make_float4(p0, p1, p2, p3);
            *(float4*)&Ps[(ty * 4 + i) * SMS + tx * 4] = pv4;
        }
        __syncthreads();

        // ---- O += P V ----
        #pragma unroll 16
        for (int k = 0; k < 64; k++) {
            float4 vv = *(const float4*)&Vs[k * SMS + tx * 4];
            float vj[4] = {vv.x, vv.y, vv.z, vv.w};
            #pragma unroll
            for (int i = 0; i < 4; i++) {
                float pr = Ps[(ty * 4 + i) * SMS + k];
                #pragma unroll
                for (int j = 0; j < 4; j++)
                    o[i][j] = fmaf(pr, vj[j], o[i][j]);
            }
        }
        __syncthreads();
    }

    // ---- epilogue: normalize, write ctx[b][t][h*64+d] ----
    #pragma unroll
    for (int i = 0; i < 4; i++) {
        float inv = 1.0f / li[i];
        float4 ov = make_float4(o[i][0] * inv, o[i][1] * inv,
                                o[i][2] * inv, o[i][3] * inv);
        *(float4*)&ctx[(size_t)(b * T_ + q0 + ty * 4 + i) * C_ + h * D_ + tx * 4] = ov;
    }
}

// ---------------------------------------------------------------------------
// Launch
// ---------------------------------------------------------------------------
extern "C" void kernel_launch(void* const* d_in, const int* in_sizes, int n_in,
                              void* d_out, int out_size)
{
    const float* x      = (const float*)d_in[0];
    const float* qkv_w  = (const float*)d_in[1];
    const float* qkv_b  = (const float*)d_in[2];
    const float* out_w  = (const float*)d_in[3];
    const float* out_b  = (const float*)d_in[4];
    // d_in[5] = attn_mask (bool) — causal, handled analytically
    float* out = (float*)d_out;

    float *qkv_ptr = nullptr, *ctx_ptr = nullptr;
    cudaGetSymbolAddress((void**)&qkv_ptr, g_qkv);
    cudaGetSymbolAddress((void**)&ctx_ptr, g_ctx);

    // 1) QKV projection: [8192,1024] x [3072,1024]^T -> [8192,3072]
    gemm_nt_kernel<<<dim3(QKV_N / 64, M_ / 64), 256>>>(
        x, qkv_w, qkv_b, qkv_ptr, M_, QKV_N, C_);

    // 2) causal flash attention -> ctx [8192,1024]
    int smem = 4 * 64 * SMS * (int)sizeof(float);   // 69632 B
    cudaFuncSetAttribute(attn_kernel,
                         cudaFuncAttributeMaxDynamicSharedMemorySize, smem);
    attn_kernel<<<dim3(T_ / 64, H_, B_), 256, smem>>>(qkv_ptr, ctx_ptr);

    // 3) output projection: [8192,1024] x [1024,1024]^T -> d_out
    gemm_nt_kernel<<<dim3(C_ / 64, M_ / 64), 256>>>(
        ctx_ptr, out_w, out_b, out, M_, C_, C_);
}

// round 3
// speedup vs baseline: 1.8314x; 1.8314x over previous
#include <cuda_runtime.h>
#include <cuda_bf16.h>
#include <cstdint>
#include <math.h>

// Problem constants
#define B_ 4
#define T_ 2048
#define C_ 1024
#define H_ 16
#define D_ 64
#define M_ (B_ * T_)          // 8192 rows
#define QKV_N (3 * C_)        // 3072

// Scratch
__device__ float g_qkv[(size_t)M_ * QKV_N];   // [B*T, 3C]
__device__ float g_ctx[(size_t)M_ * C_];      // [B*T, C]

// ===========================================================================
// helpers
// ===========================================================================
__device__ __forceinline__ uint32_t smem_u32(const void* p) {
    uint32_t a;
    asm("{ .reg .u64 t; cvta.to.shared.u64 t, %1; cvt.u32.u64 %0, t; }"
        : "=r"(a) : "l"(p));
    return a;
}

__device__ __forceinline__ void cp16(uint32_t dst, const void* src) {
    asm volatile("cp.async.cg.shared.global [%0], [%1], 16;"
        :: "r"(dst), "l"(src) : "memory");
}
#define CP_COMMIT() asm volatile("cp.async.commit_group;" ::: "memory")

__device__ __forceinline__ uint32_t f2tf32(float v) {
    uint32_t r;
    asm("cvt.rna.tf32.f32 %0, %1;" : "=r"(r) : "f"(v));
    return r;
}

__device__ __forceinline__ void mma_tf32(
    float& c0, float& c1, float& c2, float& c3,
    uint32_t a0, uint32_t a1, uint32_t a2, uint32_t a3,
    uint32_t b0, uint32_t b1)
{
    asm volatile(
        "mma.sync.aligned.m16n8k8.row.col.f32.tf32.tf32.f32 "
        "{%0,%1,%2,%3}, {%4,%5,%6,%7}, {%8,%9}, {%0,%1,%2,%3};"
        : "+f"(c0), "+f"(c1), "+f"(c2), "+f"(c3)
        : "r"(a0), "r"(a1), "r"(a2), "r"(a3), "r"(b0), "r"(b1));
}

// ===========================================================================
// tf32 mma.sync NT GEMM: C[m][n] = sum_k A[m][k]*W[n][k] + bias[n]
// CTA tile 128x128x32, 8 warps (2 x 4), warp tile 64x32, 3-stage cp.async.
// ===========================================================================
#define BM 128
#define BN 128
#define BK 32
#define LDK 36                    // BK + 4 pad (floats)
#define STG (BM * LDK)            // floats per A (or B) stage = 4608
#define NSTG 3
#define GEMM_SMEM (NSTG * 2 * STG * 4)   // 110592 bytes

__global__ void __launch_bounds__(256) gemm_mma_kernel(
    const float* __restrict__ A, const float* __restrict__ W,
    const float* __restrict__ bias, float* __restrict__ Cmat,
    int M, int N, int K)
{
    extern __shared__ __align__(16) float smf[];
    const uint32_t sb = smem_u32(smf);

    const int tid  = threadIdx.x;
    const int lane = tid & 31;
    const int wid  = tid >> 5;
    const int wm   = (wid & 1) * 64;      // warp row offset in CTA tile
    const int wn   = (wid >> 1) * 32;     // warp col offset
    const int g    = lane >> 2;           // group id 0..7
    const int tg   = lane & 3;            // thread-in-group 0..3

    const int m0 = blockIdx.y * BM;
    const int n0 = blockIdx.x * BN;
    const int NK = K / BK;

    const float* Abase = A + (size_t)m0 * K;
    const float* Wbase = W + (size_t)n0 * K;

    // per-stage load: 1024 16B chunks for A + 1024 for B, 256 threads
    auto load_stage = [&](int kc) {
        const int st = kc % NSTG;
        const uint32_t sA = sb + st * 2 * STG * 4;
        const uint32_t sB = sA + STG * 4;
        const int kOff = kc * BK;
        #pragma unroll
        for (int t = 0; t < 4; t++) {
            int idx = tid + t * 256;       // 0..1023
            int r = idx >> 3;              // row 0..127
            int c = idx & 7;               // 16B chunk (k = c*4)
            uint32_t off = (uint32_t)(r * LDK + c * 4) * 4;
            cp16(sA + off, Abase + (size_t)r * K + kOff + c * 4);
            cp16(sB + off, Wbase + (size_t)r * K + kOff + c * 4);
        }
        CP_COMMIT();
    };

    float acc[4][4][4] = {};   // [mtile][ntile][c0..c3]

    load_stage(0);
    if (NK > 1) load_stage(1);

    for (int kc = 0; kc < NK; kc++) {
        if (kc + 1 < NK) asm volatile("cp.async.wait_group 1;" ::: "memory");
        else             asm volatile("cp.async.wait_group 0;" ::: "memory");
        __syncthreads();

        if (kc + 2 < NK) load_stage(kc + 2);

        const int st = kc % NSTG;
        const float* As = smf + st * 2 * STG;
        const float* Bs = As + STG;

        #pragma unroll
        for (int ks = 0; ks < 4; ks++) {
            const int kk = ks * 8;
            uint32_t af[4][4], bf[4][2];
            #pragma unroll
            for (int i = 0; i < 4; i++) {
                const float* ap = As + (wm + i * 16 + g) * LDK + kk + tg;
                af[i][0] = f2tf32(ap[0]);
                af[i][1] = f2tf32(ap[8 * LDK]);
                af[i][2] = f2tf32(ap[4]);
                af[i][3] = f2tf32(ap[8 * LDK + 4]);
            }
            #pragma unroll
            for (int j = 0; j < 4; j++) {
                const float* bp = Bs + (wn + j * 8 + g) * LDK + kk + tg;
                bf[j][0] = f2tf32(bp[0]);
                bf[j][1] = f2tf32(bp[4]);
            }
            #pragma unroll
            for (int i = 0; i < 4; i++)
                #pragma unroll
                for (int j = 0; j < 4; j++)
                    mma_tf32(acc[i][j][0], acc[i][j][1],
                             acc[i][j][2], acc[i][j][3],
                             af[i][0], af[i][1], af[i][2], af[i][3],
                             bf[j][0], bf[j][1]);
        }
        __syncthreads();
    }

    // epilogue: c0,c1 at (row, col), (row, col+1); c2,c3 at row+8
    #pragma unroll
    for (int i = 0; i < 4; i++) {
        const int row = m0 + wm + i * 16 + g;
        #pragma unroll
        for (int j = 0; j < 4; j++) {
            const int col = n0 + wn + j * 8 + tg * 2;
            float b0 = __ldg(bias + col);
            float b1 = __ldg(bias + col + 1);
            float2 v0 = make_float2(acc[i][j][0] + b0, acc[i][j][1] + b1);
            float2 v1 = make_float2(acc[i][j][2] + b0, acc[i][j][3] + b1);
            *(float2*)&Cmat[(size_t)row * N + col] = v0;
            *(float2*)&Cmat[(size_t)(row + 8) * N + col] = v1;
        }
    }
}

// ---------------------------------------------------------------------------
// Flash attention (fp32, causal) — unchanged (verified round 1).
// ---------------------------------------------------------------------------
#define SMS 68

__device__ __forceinline__ int qk_slot(int d, int r) {
    int s4 = ((d >> 2) & 15) << 2;
    return d * SMS + (((r & 60) ^ s4) | (r & 3));
}

__global__ void __launch_bounds__(256) attn_kernel(
    const float* __restrict__ qkv, float* __restrict__ ctx)
{
    extern __shared__ __align__(16) float sm[];
    float* Qt = sm;
    float* Kt = sm + 64 * SMS;
    float* Vs = sm + 2 * 64 * SMS;
    float* Ps = sm + 3 * 64 * SMS;

    const int tid = threadIdx.x;
    const int tx = tid & 15;
    const int ty = tid >> 4;
    const int q0 = blockIdx.x * 64;
    const int h  = blockIdx.y;
    const int b  = blockIdx.z;

    const size_t base = (size_t)b * T_ * QKV_N + (size_t)h * D_;

    #pragma unroll
    for (int i = 0; i < 4; i++) {
        int idx = tid + i * 256;
        int r = idx >> 4;
        int d4 = (idx & 15) << 2;
        float4 v = *(const float4*)&qkv[base + (size_t)(q0 + r) * QKV_N + d4];
        Qt[qk_slot(d4 + 0, r)] = v.x;
        Qt[qk_slot(d4 + 1, r)] = v.y;
        Qt[qk_slot(d4 + 2, r)] = v.z;
        Qt[qk_slot(d4 + 3, r)] = v.w;
    }

    float o[4][4] = {};
    float mi[4] = {-1e30f, -1e30f, -1e30f, -1e30f};
    float li[4] = {};

    for (int k0 = 0; k0 <= q0; k0 += 64) {
        #pragma unroll
        for (int i = 0; i < 4; i++) {
            int idx = tid + i * 256;
            int r = idx >> 4;
            int d4 = (idx & 15) << 2;
            size_t rowoff = base + (size_t)(k0 + r) * QKV_N;
            float4 kv = *(const float4*)&qkv[rowoff + C_ + d4];
            Kt[qk_slot(d4 + 0, r)] = kv.x;
            Kt[qk_slot(d4 + 1, r)] = kv.y;
            Kt[qk_slot(d4 + 2, r)] = kv.z;
            Kt[qk_slot(d4 + 3, r)] = kv.w;
            float4 vv = *(const float4*)&qkv[rowoff + 2 * C_ + d4];
            *(float4*)&Vs[r * SMS + d4] = vv;
        }
        __syncthreads();

        float s[4][4] = {};
        #pragma unroll 16
        for (int d = 0; d < 64; d++) {
            int s4 = ((d >> 2) & 15) << 2;
            float4 qa = *(const float4*)&Qt[d * SMS + ((ty * 4) ^ s4)];
            float4 kb = *(const float4*)&Kt[d * SMS + ((tx * 4) ^ s4)];
            float qv[4] = {qa.x, qa.y, qa.z, qa.w};
            float kv[4] = {kb.x, kb.y, kb.z, kb.w};
            #pragma unroll
            for (int i = 0; i < 4; i++)
                #pragma unroll
                for (int j = 0; j < 4; j++)
                    s[i][j] = fmaf(qv[i], kv[j], s[i][j]);
        }

        const bool diag = (k0 == q0);
        #pragma unroll
        for (int i = 0; i < 4; i++) {
            int row = ty * 4 + i;
            #pragma unroll
            for (int j = 0; j < 4; j++) {
                float val = s[i][j] * 0.125f;
                if (diag && (tx * 4 + j > row)) val = -1e30f;
                s[i][j] = val;
            }
        }

        #pragma unroll
        for (int i = 0; i < 4; i++) {
            float mx = fmaxf(fmaxf(s[i][0], s[i][1]), fmaxf(s[i][2], s[i][3]));
            #pragma unroll
            for (int off = 1; off < 16; off <<= 1)
                mx = fmaxf(mx, __shfl_xor_sync(0xffffffffu, mx, off));
            float mnew = fmaxf(mi[i], mx);
            float alpha = __expf(mi[i] - mnew);
            float p0 = __expf(s[i][0] - mnew);
            float p1 = __expf(s[i][1] - mnew);
            float p2 = __expf(s[i][2] - mnew);
            float p3 = __expf(s[i][3] - mnew);
            float rs = (p0 + p1) + (p2 + p3);
            #pragma unroll
            for (int off = 1; off < 16; off <<= 1)
                rs += __shfl_xor_sync(0xffffffffu, rs, off);
            li[i] = li[i] * alpha + rs;
            mi[i] = mnew;
            o[i][0] *= alpha; o[i][1] *= alpha;
            o[i][2] *= alpha; o[i][3] *= alpha;
            float4 pv4 = make_float4(p0, p1, p2, p3);
            *(float4*)&Ps[(ty * 4 + i) * SMS + tx * 4] = pv4;
        }
        __syncthreads();

        #pragma unroll 16
        for (int k = 0; k < 64; k++) {
            float4 vv = *(const float4*)&Vs[k * SMS + tx * 4];
            float vj[4] = {vv.x, vv.y, vv.z, vv.w};
            #pragma unroll
            for (int i = 0; i < 4; i++) {
                float pr = Ps[(ty * 4 + i) * SMS + k];
                #pragma unroll
                for (int j = 0; j < 4; j++)
                    o[i][j] = fmaf(pr, vj[j], o[i][j]);
            }
        }
        __syncthreads();
    }

    #pragma unroll
    for (int i = 0; i < 4; i++) {
        float inv = 1.0f / li[i];
        float4 ov = make_float4(o[i][0] * inv, o[i][1] * inv,
                                o[i][2] * inv, o[i][3] * inv);
        *(float4*)&ctx[(size_t)(b * T_ + q0 + ty * 4 + i) * C_ + h * D_ + tx * 4] = ov;
    }
}

// ---------------------------------------------------------------------------
// Launch
// ---------------------------------------------------------------------------
extern "C" void kernel_launch(void* const* d_in, const int* in_sizes, int n_in,
                              void* d_out, int out_size)
{
    const float* x      = (const float*)d_in[0];
    const float* qkv_w  = (const float*)d_in[1];
    const float* qkv_b  = (const float*)d_in[2];
    const float* out_w  = (const float*)d_in[3];
    const float* out_b  = (const float*)d_in[4];
    float* out = (float*)d_out;

    float *qkv_ptr = nullptr, *ctx_ptr = nullptr;
    cudaGetSymbolAddress((void**)&qkv_ptr, g_qkv);
    cudaGetSymbolAddress((void**)&ctx_ptr, g_ctx);

    cudaFuncSetAttribute(gemm_mma_kernel,
                         cudaFuncAttributeMaxDynamicSharedMemorySize, GEMM_SMEM);

    // 1) QKV projection: [8192,1024] x [3072,1024]^T -> [8192,3072]
    gemm_mma_kernel<<<dim3(QKV_N / BN, M_ / BM), 256, GEMM_SMEM>>>(
        x, qkv_w, qkv_b, qkv_ptr, M_, QKV_N, C_);

    // 2) causal flash attention -> ctx [8192,1024]
    int smem = 4 * 64 * SMS * (int)sizeof(float);
    cudaFuncSetAttribute(attn_kernel,
                         cudaFuncAttributeMaxDynamicSharedMemorySize, smem);
    attn_kernel<<<dim3(T_ / 64, H_, B_), 256, smem>>>(qkv_ptr, ctx_ptr);

    // 3) output projection: [8192,1024] x [1024,1024]^T -> d_out
    gemm_mma_kernel<<<dim3(C_ / BN, M_ / BM), 256, GEMM_SMEM>>>(
        ctx_ptr, out_w, out_b, out, M_, C_, C_);
}

// round 4
// speedup vs baseline: 3.1924x; 1.7432x over previous
#include <cuda_runtime.h>
#include <cuda_bf16.h>
#include <cstdint>
#include <math.h>

// Problem constants
#define B_ 4
#define T_ 2048
#define C_ 1024
#define H_ 16
#define D_ 64
#define M_ (B_ * T_)          // 8192 rows
#define QKV_N (3 * C_)        // 3072

// Scratch
__device__ float g_qkv[(size_t)M_ * QKV_N];   // [B*T, 3C]
__device__ float g_ctx[(size_t)M_ * C_];      // [B*T, C]

// ===========================================================================
// helpers
// ===========================================================================
__device__ __forceinline__ uint32_t smem_u32(const void* p) {
    uint32_t a;
    asm("{ .reg .u64 t; cvta.to.shared.u64 t, %1; cvt.u32.u64 %0, t; }"
        : "=r"(a) : "l"(p));
    return a;
}

__device__ __forceinline__ void cp16(uint32_t dst, const void* src) {
    asm volatile("cp.async.cg.shared.global [%0], [%1], 16;"
        :: "r"(dst), "l"(src) : "memory");
}
#define CP_COMMIT() asm volatile("cp.async.commit_group;" ::: "memory")

__device__ __forceinline__ uint32_t f2tf32(float v) {
    uint32_t r;
    asm("cvt.rna.tf32.f32 %0, %1;" : "=r"(r) : "f"(v));
    return r;
}

__device__ __forceinline__ void mma_tf32(
    float& c0, float& c1, float& c2, float& c3,
    uint32_t a0, uint32_t a1, uint32_t a2, uint32_t a3,
    uint32_t b0, uint32_t b1)
{
    asm volatile(
        "mma.sync.aligned.m16n8k8.row.col.f32.tf32.tf32.f32 "
        "{%0,%1,%2,%3}, {%4,%5,%6,%7}, {%8,%9}, {%0,%1,%2,%3};"
        : "+f"(c0), "+f"(c1), "+f"(c2), "+f"(c3)
        : "r"(a0), "r"(a1), "r"(a2), "r"(a3), "r"(b0), "r"(b1));
}

// ===========================================================================
// tf32 mma.sync NT GEMM: C[m][n] = sum_k A[m][k]*W[n][k] + bias[n]
// CTA tile 128x128x32, 8 warps, warp tile 64x32, 2-stage cp.async,
// 2 CTAs/SM.
// ===========================================================================
#define BM 128
#define BN 128
#define BK 32
#define LDK 36                    // BK + 4 pad (floats)
#define STG (BM * LDK)            // 4608 floats per A (or B) stage
#define NSTG 2
#define GEMM_SMEM (NSTG * 2 * STG * 4)   // 73728 bytes

__global__ void __launch_bounds__(256, 2) gemm_mma_kernel(
    const float* __restrict__ A, const float* __restrict__ W,
    const float* __restrict__ bias, float* __restrict__ Cmat,
    int M, int N, int K)
{
    extern __shared__ __align__(16) float smf[];
    const uint32_t sb = smem_u32(smf);

    const int tid  = threadIdx.x;
    const int lane = tid & 31;
    const int wid  = tid >> 5;
    const int wm   = (wid & 1) * 64;
    const int wn   = (wid >> 1) * 32;
    const int g    = lane >> 2;
    const int tg   = lane & 3;

    const int m0 = blockIdx.y * BM;
    const int n0 = blockIdx.x * BN;
    const int NK = K / BK;

    const float* Abase = A + (size_t)m0 * K;
    const float* Wbase = W + (size_t)n0 * K;

    auto load_stage = [&](int kc) {
        const int st = kc % NSTG;
        const uint32_t sA = sb + st * 2 * STG * 4;
        const uint32_t sB = sA + STG * 4;
        const int kOff = kc * BK;
        #pragma unroll
        for (int t = 0; t < 4; t++) {
            int idx = tid + t * 256;
            int r = idx >> 3;
            int c = idx & 7;
            uint32_t off = (uint32_t)(r * LDK + c * 4) * 4;
            cp16(sA + off, Abase + (size_t)r * K + kOff + c * 4);
            cp16(sB + off, Wbase + (size_t)r * K + kOff + c * 4);
        }
        CP_COMMIT();
    };

    float acc[4][4][4] = {};

    load_stage(0);
    if (NK > 1) load_stage(1);

    for (int kc = 0; kc < NK; kc++) {
        if (kc + 1 < NK) asm volatile("cp.async.wait_group 1;" ::: "memory");
        else             asm volatile("cp.async.wait_group 0;" ::: "memory");
        __syncthreads();

        const int st = kc % NSTG;
        const float* As = smf + st * 2 * STG;
        const float* Bs = As + STG;

        #pragma unroll
        for (int ks = 0; ks < 4; ks++) {
            const int kk = ks * 8;
            uint32_t af[4][4], bf[4][2];
            #pragma unroll
            for (int i = 0; i < 4; i++) {
                const float* ap = As + (wm + i * 16 + g) * LDK + kk + tg;
                af[i][0] = f2tf32(ap[0]);
                af[i][1] = f2tf32(ap[8 * LDK]);
                af[i][2] = f2tf32(ap[4]);
                af[i][3] = f2tf32(ap[8 * LDK + 4]);
            }
            #pragma unroll
            for (int j = 0; j < 4; j++) {
                const float* bp = Bs + (wn + j * 8 + g) * LDK + kk + tg;
                bf[j][0] = f2tf32(bp[0]);
                bf[j][1] = f2tf32(bp[4]);
            }
            #pragma unroll
            for (int i = 0; i < 4; i++)
                #pragma unroll
                for (int j = 0; j < 4; j++)
                    mma_tf32(acc[i][j][0], acc[i][j][1],
                             acc[i][j][2], acc[i][j][3],
                             af[i][0], af[i][1], af[i][2], af[i][3],
                             bf[j][0], bf[j][1]);
        }
        __syncthreads();

        if (kc + 2 < NK) load_stage(kc + 2);
    }

    #pragma unroll
    for (int i = 0; i < 4; i++) {
        const int row = m0 + wm + i * 16 + g;
        #pragma unroll
        for (int j = 0; j < 4; j++) {
            const int col = n0 + wn + j * 8 + tg * 2;
            float b0 = __ldg(bias + col);
            float b1 = __ldg(bias + col + 1);
            float2 v0 = make_float2(acc[i][j][0] + b0, acc[i][j][1] + b1);
            float2 v1 = make_float2(acc[i][j][2] + b0, acc[i][j][3] + b1);
            *(float2*)&Cmat[(size_t)row * N + col] = v0;
            *(float2*)&Cmat[(size_t)(row + 8) * N + col] = v1;
        }
    }
}

// ===========================================================================
// Tensor-core flash attention (tf32 mma.sync, causal).
// CTA = (b, h, 64-row q-tile), 128 threads (4 warps, 16 q-rows each).
// k-permutation trick: mma slot k = tg maps to data k = tg*2, slot k = tg+4
// maps to data k = tg*2+1, applied identically to A and B fragments — valid
// because the mma's k-sum is permutation-invariant. All fragments then load
// from natural row-major smem (float2 for Q/K/P, 2 scalars for V).
// ===========================================================================
#define ALD 68
#define ATT_TILE (64 * ALD)                  // floats per 64x64 tile
#define ATT_SMEM (6 * ATT_TILE * 4)          // Q + 2K + 2V + P = 104448 B

__global__ void __launch_bounds__(128) attn_tc_kernel(
    const float* __restrict__ qkv, float* __restrict__ ctx)
{
    extern __shared__ __align__(16) float sm[];
    float* Qs = sm;                          // [64][ALD]
    float* Ks = sm + ATT_TILE;               // [2][64][ALD]
    float* Vs = sm + 3 * ATT_TILE;           // [2][64][ALD]
    float* Ps = sm + 5 * ATT_TILE;           // [64][ALD]
    const uint32_t sb = smem_u32(sm);

    const int tid  = threadIdx.x;
    const int lane = tid & 31;
    const int wid  = tid >> 5;
    const int g    = lane >> 2;
    const int tg   = lane & 3;
    const int wm   = wid * 16;

    const int q0 = blockIdx.x * 64;
    const int h  = blockIdx.y;
    const int b  = blockIdx.z;
    const int nk = blockIdx.x + 1;           // causal: k-tiles 0..q0/64

    const size_t base = (size_t)b * T_ * QKV_N + (size_t)h * D_;

    // tile loader: 64x64 floats, 8 x float4 per thread
    auto load_tile = [&](int fbase, const float* gsrc) {
        #pragma unroll
        for (int t = 0; t < 8; t++) {
            int idx = tid + t * 128;
            int r = idx >> 4;
            int c4 = (idx & 15) << 2;
            cp16(sb + (uint32_t)(fbase + r * ALD + c4) * 4,
                 gsrc + (size_t)r * QKV_N + c4);
        }
    };

    // prologue: G0 = {Q, K0, V0}; G1 = {K1, V1}
    load_tile(0, qkv + base + (size_t)q0 * QKV_N);
    load_tile(ATT_TILE, qkv + base + C_);
    load_tile(3 * ATT_TILE, qkv + base + 2 * C_);
    CP_COMMIT();
    if (nk > 1) {
        load_tile(2 * ATT_TILE, qkv + base + (size_t)64 * QKV_N + C_);
        load_tile(4 * ATT_TILE, qkv + base + (size_t)64 * QKV_N + 2 * C_);
        CP_COMMIT();
    }

    float o[8][4] = {};
    float mi[2] = {-1e30f, -1e30f};
    float li[2] = {0.0f, 0.0f};

    for (int it = 0; it < nk; it++) {
        if (it + 1 < nk) asm volatile("cp.async.wait_group 1;" ::: "memory");
        else             asm volatile("cp.async.wait_group 0;" ::: "memory");
        __syncthreads();

        const int cur = it & 1;
        const int k0 = it * 64;
        const float* Kb = Ks + cur * ATT_TILE;
        const float* Vb = Vs + cur * ATT_TILE;

        // ---- S = Q K^T ----
        float s[8][4] = {};
        #pragma unroll
        for (int ks = 0; ks < 8; ks++) {
            const int kk = ks * 8;
            const float* qp = Qs + (wm + g) * ALD + kk + tg * 2;
            float2 qa = *(const float2*)qp;
            float2 qb = *(const float2*)(qp + 8 * ALD);
            uint32_t a0 = f2tf32(qa.x), a2 = f2tf32(qa.y);
            uint32_t a1 = f2tf32(qb.x), a3 = f2tf32(qb.y);
            #pragma unroll
            for (int j = 0; j < 8; j++) {
                float2 kb2 = *(const float2*)(Kb + (j * 8 + g) * ALD + kk + tg * 2);
                mma_tf32(s[j][0], s[j][1], s[j][2], s[j][3],
                         a0, a1, a2, a3, f2tf32(kb2.x), f2tf32(kb2.y));
            }
        }

        // ---- scale + causal mask + online softmax ----
        const bool diag = (it == nk - 1);
        #pragma unroll
        for (int h2 = 0; h2 < 2; h2++) {
            const int rowg = q0 + wm + g + h2 * 8;
            float mx = -1e30f;
            #pragma unroll
            for (int j = 0; j < 8; j++) {
                float v0 = s[j][h2 * 2 + 0] * 0.125f;
                float v1 = s[j][h2 * 2 + 1] * 0.125f;
                if (diag) {
                    int col = k0 + j * 8 + tg * 2;
                    if (col > rowg)     v0 = -1e30f;
                    if (col + 1 > rowg) v1 = -1e30f;
                }
                s[j][h2 * 2 + 0] = v0;
                s[j][h2 * 2 + 1] = v1;
                mx = fmaxf(mx, fmaxf(v0, v1));
            }
            mx = fmaxf(mx, __shfl_xor_sync(0xffffffffu, mx, 1));
            mx = fmaxf(mx, __shfl_xor_sync(0xffffffffu, mx, 2));

            float mnew = fmaxf(mi[h2], mx);
            float alpha = __expf(mi[h2] - mnew);
            float rs = 0.0f;
            #pragma unroll
            for (int j = 0; j < 8; j++) {
                float p0 = __expf(s[j][h2 * 2 + 0] - mnew);
                float p1 = __expf(s[j][h2 * 2 + 1] - mnew);
                s[j][h2 * 2 + 0] = p0;
                s[j][h2 * 2 + 1] = p1;
                rs += p0 + p1;
                o[j][h2 * 2 + 0] *= alpha;
                o[j][h2 * 2 + 1] *= alpha;
            }
            rs += __shfl_xor_sync(0xffffffffu, rs, 1);
            rs += __shfl_xor_sync(0xffffffffu, rs, 2);
            li[h2] = li[h2] * alpha + rs;
            mi[h2] = mnew;

            // write P rows to smem (warp-private region)
            #pragma unroll
            for (int j = 0; j < 8; j++) {
                *(float2*)&Ps[(wm + g + h2 * 8) * ALD + j * 8 + tg * 2] =
                    make_float2(s[j][h2 * 2 + 0], s[j][h2 * 2 + 1]);
            }
        }
        __syncwarp();

        // ---- O += P V ----
        #pragma unroll
        for (int ks = 0; ks < 8; ks++) {
            const int kk = ks * 8;
            const float* pp = Ps + (wm + g) * ALD + kk + tg * 2;
            float2 pa = *(const float2*)pp;
            float2 pb = *(const float2*)(pp + 8 * ALD);
            uint32_t a0 = f2tf32(pa.x), a2 = f2tf32(pa.y);
            uint32_t a1 = f2tf32(pb.x), a3 = f2tf32(pb.y);
            #pragma unroll
            for (int j = 0; j < 8; j++) {
                float b0f = Vb[(kk + tg * 2) * ALD + j * 8 + g];
                float b1f = Vb[(kk + tg * 2 + 1) * ALD + j * 8 + g];
                mma_tf32(o[j][0], o[j][1], o[j][2], o[j][3],
                         a0, a1, a2, a3, f2tf32(b0f), f2tf32(b1f));
            }
        }
        __syncthreads();

        // prefetch tile it+2 into buffer cur (now free)
        if (it + 2 < nk) {
            const size_t roff = base + (size_t)(it + 2) * 64 * QKV_N;
            load_tile(ATT_TILE + cur * ATT_TILE, qkv + roff + C_);
            load_tile(3 * ATT_TILE + cur * ATT_TILE, qkv + roff + 2 * C_);
            CP_COMMIT();
        }
    }

    // ---- epilogue ----
    #pragma unroll
    for (int h2 = 0; h2 < 2; h2++) {
        const float inv = 1.0f / li[h2];
        const size_t row = (size_t)(b * T_ + q0 + wm + g + h2 * 8);
        #pragma unroll
        for (int j = 0; j < 8; j++) {
            float2 v = make_float2(o[j][h2 * 2 + 0] * inv,
                                   o[j][h2 * 2 + 1] * inv);
            *(float2*)&ctx[row * C_ + h * D_ + j * 8 + tg * 2] = v;
        }
    }
}

// ---------------------------------------------------------------------------
// Launch
// ---------------------------------------------------------------------------
extern "C" void kernel_launch(void* const* d_in, const int* in_sizes, int n_in,
                              void* d_out, int out_size)
{
    const float* x      = (const float*)d_in[0];
    const float* qkv_w  = (const float*)d_in[1];
    const float* qkv_b  = (const float*)d_in[2];
    const float* out_w  = (const float*)d_in[3];
    const float* out_b  = (const float*)d_in[4];
    float* out = (float*)d_out;

    float *qkv_ptr = nullptr, *ctx_ptr = nullptr;
    cudaGetSymbolAddress((void**)&qkv_ptr, g_qkv);
    cudaGetSymbolAddress((void**)&ctx_ptr, g_ctx);

    cudaFuncSetAttribute(gemm_mma_kernel,
                         cudaFuncAttributeMaxDynamicSharedMemorySize, GEMM_SMEM);
    cudaFuncSetAttribute(attn_tc_kernel,
                         cudaFuncAttributeMaxDynamicSharedMemorySize, ATT_SMEM);

    // 1) QKV projection
    gemm_mma_kernel<<<dim3(QKV_N / BN, M_ / BM), 256, GEMM_SMEM>>>(
        x, qkv_w, qkv_b, qkv_ptr, M_, QKV_N, C_);

    // 2) causal flash attention (tensor cores)
    attn_tc_kernel<<<dim3(T_ / 64, H_, B_), 128, ATT_SMEM>>>(qkv_ptr, ctx_ptr);

    // 3) output projection
    gemm_mma_kernel<<<dim3(C_ / BN, M_ / BM), 256, GEMM_SMEM>>>(
        ctx_ptr, out_w, out_b, out, M_, C_, C_);
}

// round 5
// speedup vs baseline: 3.4595x; 1.0837x over previous
#include <cuda_runtime.h>
#include <cuda_bf16.h>
#include <cstdint>
#include <math.h>

// Problem constants
#define B_ 4
#define T_ 2048
#define C_ 1024
#define H_ 16
#define D_ 64
#define M_ (B_ * T_)          // 8192 rows
#define QKV_N (3 * C_)        // 3072

// Scratch
__device__ float g_qkv[(size_t)M_ * QKV_N];   // [B*T, 3C]
__device__ float g_ctx[(size_t)M_ * C_];      // [B*T, C]

// ===========================================================================
// helpers
// ===========================================================================
__device__ __forceinline__ uint32_t smem_u32(const void* p) {
    uint32_t a;
    asm("{ .reg .u64 t; cvta.to.shared.u64 t, %1; cvt.u32.u64 %0, t; }"
        : "=r"(a) : "l"(p));
    return a;
}

__device__ __forceinline__ void cp16(uint32_t dst, const void* src) {
    asm volatile("cp.async.cg.shared.global [%0], [%1], 16;"
        :: "r"(dst), "l"(src) : "memory");
}
#define CP_COMMIT() asm volatile("cp.async.commit_group;" ::: "memory")

__device__ __forceinline__ uint32_t f2tf32(float v) {
    uint32_t r;
    asm("cvt.rna.tf32.f32 %0, %1;" : "=r"(r) : "f"(v));
    return r;
}

__device__ __forceinline__ void mma_tf32(
    float& c0, float& c1, float& c2, float& c3,
    uint32_t a0, uint32_t a1, uint32_t a2, uint32_t a3,
    uint32_t b0, uint32_t b1)
{
    asm volatile(
        "mma.sync.aligned.m16n8k8.row.col.f32.tf32.tf32.f32 "
        "{%0,%1,%2,%3}, {%4,%5,%6,%7}, {%8,%9}, {%0,%1,%2,%3};"
        : "+f"(c0), "+f"(c1), "+f"(c2), "+f"(c3)
        : "r"(a0), "r"(a1), "r"(a2), "r"(a3), "r"(b0), "r"(b1));
}

// ===========================================================================
// tf32 mma.sync NT GEMM (unchanged from round 4 — passing @ tensor 47.5%)
// ===========================================================================
#define BM 128
#define BN 128
#define BK 32
#define LDK 36
#define STG (BM * LDK)
#define NSTG 2
#define GEMM_SMEM (NSTG * 2 * STG * 4)   // 73728 bytes

__global__ void __launch_bounds__(256, 2) gemm_mma_kernel(
    const float* __restrict__ A, const float* __restrict__ W,
    const float* __restrict__ bias, float* __restrict__ Cmat,
    int M, int N, int K)
{
    extern __shared__ __align__(16) float smf[];
    const uint32_t sb = smem_u32(smf);

    const int tid  = threadIdx.x;
    const int lane = tid & 31;
    const int wid  = tid >> 5;
    const int wm   = (wid & 1) * 64;
    const int wn   = (wid >> 1) * 32;
    const int g    = lane >> 2;
    const int tg   = lane & 3;

    const int m0 = blockIdx.y * BM;
    const int n0 = blockIdx.x * BN;
    const int NK = K / BK;

    const float* Abase = A + (size_t)m0 * K;
    const float* Wbase = W + (size_t)n0 * K;

    auto load_stage = [&](int kc) {
        const int st = kc % NSTG;
        const uint32_t sA = sb + st * 2 * STG * 4;
        const uint32_t sB = sA + STG * 4;
        const int kOff = kc * BK;
        #pragma unroll
        for (int t = 0; t < 4; t++) {
            int idx = tid + t * 256;
            int r = idx >> 3;
            int c = idx & 7;
            uint32_t off = (uint32_t)(r * LDK + c * 4) * 4;
            cp16(sA + off, Abase + (size_t)r * K + kOff + c * 4);
            cp16(sB + off, Wbase + (size_t)r * K + kOff + c * 4);
        }
        CP_COMMIT();
    };

    float acc[4][4][4] = {};

    load_stage(0);
    if (NK > 1) load_stage(1);

    for (int kc = 0; kc < NK; kc++) {
        if (kc + 1 < NK) asm volatile("cp.async.wait_group 1;" ::: "memory");
        else             asm volatile("cp.async.wait_group 0;" ::: "memory");
        __syncthreads();

        const int st = kc % NSTG;
        const float* As = smf + st * 2 * STG;
        const float* Bs = As + STG;

        #pragma unroll
        for (int ks = 0; ks < 4; ks++) {
            const int kk = ks * 8;
            uint32_t af[4][4], bf[4][2];
            #pragma unroll
            for (int i = 0; i < 4; i++) {
                const float* ap = As + (wm + i * 16 + g) * LDK + kk + tg;
                af[i][0] = f2tf32(ap[0]);
                af[i][1] = f2tf32(ap[8 * LDK]);
                af[i][2] = f2tf32(ap[4]);
                af[i][3] = f2tf32(ap[8 * LDK + 4]);
            }
            #pragma unroll
            for (int j = 0; j < 4; j++) {
                const float* bp = Bs + (wn + j * 8 + g) * LDK + kk + tg;
                bf[j][0] = f2tf32(bp[0]);
                bf[j][1] = f2tf32(bp[4]);
            }
            #pragma unroll
            for (int i = 0; i < 4; i++)
                #pragma unroll
                for (int j = 0; j < 4; j++)
                    mma_tf32(acc[i][j][0], acc[i][j][1],
                             acc[i][j][2], acc[i][j][3],
                             af[i][0], af[i][1], af[i][2], af[i][3],
                             bf[j][0], bf[j][1]);
        }
        __syncthreads();

        if (kc + 2 < NK) load_stage(kc + 2);
    }

    #pragma unroll
    for (int i = 0; i < 4; i++) {
        const int row = m0 + wm + i * 16 + g;
        #pragma unroll
        for (int j = 0; j < 4; j++) {
            const int col = n0 + wn + j * 8 + tg * 2;
            float b0 = __ldg(bias + col);
            float b1 = __ldg(bias + col + 1);
            float2 v0 = make_float2(acc[i][j][0] + b0, acc[i][j][1] + b1);
            float2 v1 = make_float2(acc[i][j][2] + b0, acc[i][j][3] + b1);
            *(float2*)&Cmat[(size_t)row * N + col] = v0;
            *(float2*)&Cmat[(size_t)(row + 8) * N + col] = v1;
        }
    }
}

// ===========================================================================
// Tensor-core flash attention v2 (tf32 mma.sync, causal).
// CTA = (b, h, 256-row q-block), 512 threads = 16 warps x 16 q-rows.
// K/V tiles (64x64) double-buffered; each tile's load is amortized over
// 256 q-rows (4x fewer LDGSTS per MMA than q=64). P never leaves registers:
// with the k-permutation fragment mapping, the S/P mma OUTPUT layout equals
// the next mma's A-operand layout (a0=s[j][0], a1=s[j][2], a2=s[j][1],
// a3=s[j][3]). Warps fully above the diagonal skip a tile's compute.
// ===========================================================================
#define QB 256
#define ALD 68
#define KV_TILE (64 * ALD)                       // floats per 64x64 tile
#define Q_FLOATS (QB * ALD)                      // 17408
#define ATT_SMEM ((Q_FLOATS + 4 * KV_TILE) * 4)  // 139264 B

__global__ void __launch_bounds__(512, 1) attn_tc_kernel(
    const float* __restrict__ qkv, float* __restrict__ ctx)
{
    extern __shared__ __align__(16) float sm[];
    float* Qs = sm;                                  // [256][ALD]
    float* Ks = sm + Q_FLOATS;                       // [2][64][ALD]
    float* Vs = sm + Q_FLOATS + 2 * KV_TILE;         // [2][64][ALD]
    const uint32_t sb = smem_u32(sm);

    const int tid  = threadIdx.x;
    const int lane = tid & 31;
    const int wid  = tid >> 5;
    const int g    = lane >> 2;
    const int tg   = lane & 3;
    const int wm   = wid * 16;                       // warp's q-row offset

    const int bh = blockIdx.x;                       // 0..63
    const int b  = bh >> 4;
    const int h  = bh & 15;
    const int qblock = 7 - (int)blockIdx.y;          // heavy blocks first
    const int q0 = qblock << 8;
    const int nk = (qblock + 1) * 4;                 // causal k-tiles

    const size_t base = (size_t)b * T_ * QKV_N + (size_t)h * D_;

    // K/V tile loader: 1024 x 16B chunks, 512 threads -> 2 chunks each
    auto load_kv = [&](int fbase, const float* gsrc) {
        #pragma unroll
        for (int t = 0; t < 2; t++) {
            int idx = tid + t * 512;
            int r = idx >> 4;
            int c4 = (idx & 15) << 2;
            cp16(sb + (uint32_t)(fbase + r * ALD + c4) * 4,
                 gsrc + (size_t)r * QKV_N + c4);
        }
    };

    // prologue: G0 = {Q(256 rows), K0, V0}; G1 = {K1, V1}
    {
        const float* qsrc = qkv + base + (size_t)q0 * QKV_N;
        #pragma unroll
        for (int t = 0; t < 8; t++) {
            int idx = tid + t * 512;
            int r = idx >> 4;
            int c4 = (idx & 15) << 2;
            cp16(sb + (uint32_t)(r * ALD + c4) * 4,
                 qsrc + (size_t)r * QKV_N + c4);
        }
        load_kv(Q_FLOATS, qkv + base + C_);
        load_kv(Q_FLOATS + 2 * KV_TILE, qkv + base + 2 * C_);
        CP_COMMIT();
        if (nk > 1) {
            load_kv(Q_FLOATS + KV_TILE, qkv + base + (size_t)64 * QKV_N + C_);
            load_kv(Q_FLOATS + 3 * KV_TILE,
                    qkv + base + (size_t)64 * QKV_N + 2 * C_);
            CP_COMMIT();
        }
    }
    if (nk > 1) asm volatile("cp.async.wait_group 1;" ::: "memory");
    else        asm volatile("cp.async.wait_group 0;" ::: "memory");
    __syncthreads();

    float o[8][4] = {};
    float mi[2] = {-1e30f, -1e30f};
    float li[2] = {0.0f, 0.0f};

    for (int it = 0; it < nk; it++) {
        const int cur = it & 1;
        const int k0 = it * 64;
        const float* Kb = Ks + cur * KV_TILE;
        const float* Vb = Vs + cur * KV_TILE;

        // warp entirely above diagonal for this tile -> skip compute
        if (k0 <= q0 + wm + 15) {
            // ---- S = Q K^T ----
            float s[8][4] = {};
            #pragma unroll
            for (int ks = 0; ks < 8; ks++) {
                const int kk = ks * 8;
                const float* qp = Qs + (wm + g) * ALD + kk + tg * 2;
                float2 qa = *(const float2*)qp;
                float2 qb = *(const float2*)(qp + 8 * ALD);
                uint32_t a0 = f2tf32(qa.x), a2 = f2tf32(qa.y);
                uint32_t a1 = f2tf32(qb.x), a3 = f2tf32(qb.y);
                #pragma unroll
                for (int j = 0; j < 8; j++) {
                    float2 kb2 = *(const float2*)
                        (Kb + (j * 8 + g) * ALD + kk + tg * 2);
                    mma_tf32(s[j][0], s[j][1], s[j][2], s[j][3],
                             a0, a1, a2, a3, f2tf32(kb2.x), f2tf32(kb2.y));
                }
            }

            // ---- scale + causal mask + online softmax ----
            const bool diag = (k0 + 63 > q0 + wm);
            #pragma unroll
            for (int h2 = 0; h2 < 2; h2++) {
                const int rowg = q0 + wm + g + h2 * 8;
                float mx = -1e30f;
                #pragma unroll
                for (int j = 0; j < 8; j++) {
                    float v0 = s[j][h2 * 2 + 0] * 0.125f;
                    float v1 = s[j][h2 * 2 + 1] * 0.125f;
                    if (diag) {
                        int col = k0 + j * 8 + tg * 2;
                        if (col > rowg)     v0 = -1e30f;
                        if (col + 1 > rowg) v1 = -1e30f;
                    }
                    s[j][h2 * 2 + 0] = v0;
                    s[j][h2 * 2 + 1] = v1;
                    mx = fmaxf(mx, fmaxf(v0, v1));
                }
                mx = fmaxf(mx, __shfl_xor_sync(0xffffffffu, mx, 1));
                mx = fmaxf(mx, __shfl_xor_sync(0xffffffffu, mx, 2));

                float mnew = fmaxf(mi[h2], mx);
                float alpha = __expf(mi[h2] - mnew);
                float rs = 0.0f;
                #pragma unroll
                for (int j = 0; j < 8; j++) {
                    float p0 = __expf(s[j][h2 * 2 + 0] - mnew);
                    float p1 = __expf(s[j][h2 * 2 + 1] - mnew);
                    s[j][h2 * 2 + 0] = p0;
                    s[j][h2 * 2 + 1] = p1;
                    rs += p0 + p1;
                    o[j][h2 * 2 + 0] *= alpha;
                    o[j][h2 * 2 + 1] *= alpha;
                }
                rs += __shfl_xor_sync(0xffffffffu, rs, 1);
                rs += __shfl_xor_sync(0xffffffffu, rs, 2);
                li[h2] = li[h2] * alpha + rs;
                mi[h2] = mnew;
            }

            // ---- O += P V  (P fragments taken directly from s registers) ----
            #pragma unroll
            for (int j = 0; j < 8; j++) {
                uint32_t a0 = f2tf32(s[j][0]);
                uint32_t a1 = f2tf32(s[j][2]);
                uint32_t a2 = f2tf32(s[j][1]);
                uint32_t a3 = f2tf32(s[j][3]);
                #pragma unroll
                for (int n = 0; n < 8; n++) {
                    float b0f = Vb[(j * 8 + tg * 2) * ALD + n * 8 + g];
                    float b1f = Vb[(j * 8 + tg * 2 + 1) * ALD + n * 8 + g];
                    mma_tf32(o[n][0], o[n][1], o[n][2], o[n][3],
                             a0, a1, a2, a3, f2tf32(b0f), f2tf32(b1f));
                }
            }
        }
        __syncthreads();   // all warps done reading buffer `cur`

        if (it + 2 < nk) {
            const size_t roff = base + (size_t)(it + 2) * 64 * QKV_N;
            load_kv(Q_FLOATS + cur * KV_TILE, qkv + roff + C_);
            load_kv(Q_FLOATS + 2 * KV_TILE + cur * KV_TILE,
                    qkv + roff + 2 * C_);
            CP_COMMIT();
        }
        if (it + 1 < nk) {
            if (it + 2 < nk) asm volatile("cp.async.wait_group 1;" ::: "memory");
            else             asm volatile("cp.async.wait_group 0;" ::: "memory");
            __syncthreads();
        }
    }

    // ---- epilogue ----
    #pragma unroll
    for (int h2 = 0; h2 < 2; h2++) {
        const float inv = 1.0f / li[h2];
        const size_t row = (size_t)(b * T_ + q0 + wm + g + h2 * 8);
        #pragma unroll
        for (int j = 0; j < 8; j++) {
            float2 v = make_float2(o[j][h2 * 2 + 0] * inv,
                                   o[j][h2 * 2 + 1] * inv);
            *(float2*)&ctx[row * C_ + h * D_ + j * 8 + tg * 2] = v;
        }
    }
}

// ---------------------------------------------------------------------------
// Launch
// ---------------------------------------------------------------------------
extern "C" void kernel_launch(void* const* d_in, const int* in_sizes, int n_in,
                              void* d_out, int out_size)
{
    const float* x      = (const float*)d_in[0];
    const float* qkv_w  = (const float*)d_in[1];
    const float* qkv_b  = (const float*)d_in[2];
    const float* out_w  = (const float*)d_in[3];
    const float* out_b  = (const float*)d_in[4];
    float* out = (float*)d_out;

    float *qkv_ptr = nullptr, *ctx_ptr = nullptr;
    cudaGetSymbolAddress((void**)&qkv_ptr, g_qkv);
    cudaGetSymbolAddress((void**)&ctx_ptr, g_ctx);

    cudaFuncSetAttribute(gemm_mma_kernel,
                         cudaFuncAttributeMaxDynamicSharedMemorySize, GEMM_SMEM);
    cudaFuncSetAttribute(attn_tc_kernel,
                         cudaFuncAttributeMaxDynamicSharedMemorySize, ATT_SMEM);

    // 1) QKV projection
    gemm_mma_kernel<<<dim3(QKV_N / BN, M_ / BM), 256, GEMM_SMEM>>>(
        x, qkv_w, qkv_b, qkv_ptr, M_, QKV_N, C_);

    // 2) causal flash attention (tensor cores, 256-row q-blocks)
    attn_tc_kernel<<<dim3(H_ * B_, T_ / QB), 512, ATT_SMEM>>>(qkv_ptr, ctx_ptr);

    // 3) output projection
    gemm_mma_kernel<<<dim3(C_ / BN, M_ / BM), 256, GEMM_SMEM>>>(
        ctx_ptr, out_w, out_b, out, M_, C_, C_);
}